// round 5
// baseline (speedup 1.0000x reference)
#include <cuda_runtime.h>
#include <cuda_bf16.h>
#include <math.h>

// Problem constants
#define S_   2048
#define E_   4096
#define H_   16
#define D_   256
#define RD_  64

// GEMM tiling
#define BM 128
#define BN 128
#define BK 8
#define TM 8
#define TN 8
#define NTHREADS 256

// ---------------------------------------------------------------------------
// Scratch (device globals: allocation-guard-safe)
// ---------------------------------------------------------------------------
__device__ float g_q[(size_t)S_ * E_];
__device__ float g_k[(size_t)S_ * E_];
__device__ float g_v[(size_t)S_ * E_];
__device__ float g_attn[(size_t)S_ * E_];
__device__ float g_scores[(size_t)H_ * S_ * S_];   // 256 MB, reused in-place for probs

// ---------------------------------------------------------------------------
// Generic 128x128 fp32 GEMM tile core.
//   C[m0:m0+128, n0:n0+128] = sum_{k=k0}^{k1} A[m][k] * B'[k][n]
//   TRANSB=false:  B'[k][n] = B[k*ldb + n]   (NN)
//   TRANSB=true :  B'[k][n] = B[n*ldb + k]   (NT, i.e. C = A * B^T)
// Requires: k1-k0 multiple of BK, all leading dims multiple of 4,
//           pointers 16B aligned at the accessed offsets (true for all uses).
// ---------------------------------------------------------------------------
template <bool TRANSB>
__device__ __forceinline__ void gemm_tile(
    const float* __restrict__ A, int lda,
    const float* __restrict__ B, int ldb,
    float* __restrict__ C, int ldc,
    int m0, int n0, int k0, int k1)
{
    __shared__ float As[BK][BM];
    __shared__ float Bs[BK][BN];

    const int tid = threadIdx.x;
    const int tx = tid & 15;   // 0..15  -> column group
    const int ty = tid >> 4;   // 0..15  -> row group

    float acc[TM][TN];
#pragma unroll
    for (int i = 0; i < TM; ++i)
#pragma unroll
        for (int j = 0; j < TN; ++j) acc[i][j] = 0.0f;

    // A load map: each thread loads one float4 of a 128x8 tile
    const int aRow = tid >> 1;          // 0..127
    const int aCol = (tid & 1) * 4;     // 0 or 4

    for (int kt = k0; kt < k1; kt += BK) {
        // ---- load A tile (transposed into As[k][m]) ----
        {
            float4 av = *(const float4*)&A[(size_t)(m0 + aRow) * lda + kt + aCol];
            As[aCol + 0][aRow] = av.x;
            As[aCol + 1][aRow] = av.y;
            As[aCol + 2][aRow] = av.z;
            As[aCol + 3][aRow] = av.w;
        }
        // ---- load B tile ----
        if (TRANSB) {
            const int bN = tid >> 1;          // 0..127
            const int bK = (tid & 1) * 4;     // 0 or 4
            float4 bv = *(const float4*)&B[(size_t)(n0 + bN) * ldb + kt + bK];
            Bs[bK + 0][bN] = bv.x;
            Bs[bK + 1][bN] = bv.y;
            Bs[bK + 2][bN] = bv.z;
            Bs[bK + 3][bN] = bv.w;
        } else {
            const int bRow = tid >> 5;          // 0..7
            const int bCol = (tid & 31) * 4;    // 0..124
            float4 bv = *(const float4*)&B[(size_t)(kt + bRow) * ldb + n0 + bCol];
            *(float4*)&Bs[bRow][bCol] = bv;
        }
        __syncthreads();

        // ---- compute ----
#pragma unroll
        for (int kk = 0; kk < BK; ++kk) {
            float a[TM], b[TN];
            float4 t;
            t = *(const float4*)&As[kk][ty * TM];     a[0]=t.x; a[1]=t.y; a[2]=t.z; a[3]=t.w;
            t = *(const float4*)&As[kk][ty * TM + 4]; a[4]=t.x; a[5]=t.y; a[6]=t.z; a[7]=t.w;
            t = *(const float4*)&Bs[kk][tx * TN];     b[0]=t.x; b[1]=t.y; b[2]=t.z; b[3]=t.w;
            t = *(const float4*)&Bs[kk][tx * TN + 4]; b[4]=t.x; b[5]=t.y; b[6]=t.z; b[7]=t.w;
#pragma unroll
            for (int i = 0; i < TM; ++i)
#pragma unroll
                for (int j = 0; j < TN; ++j)
                    acc[i][j] = fmaf(a[i], b[j], acc[i][j]);
        }
        __syncthreads();
    }

    // ---- epilogue ----
#pragma unroll
    for (int i = 0; i < TM; ++i) {
        float* cp = &C[(size_t)(m0 + ty * TM + i) * ldc + n0 + tx * TN];
        float4 v0 = make_float4(acc[i][0], acc[i][1], acc[i][2], acc[i][3]);
        float4 v1 = make_float4(acc[i][4], acc[i][5], acc[i][6], acc[i][7]);
        *(float4*)cp       = v0;
        *(float4*)(cp + 4) = v1;
    }
}

// ---------------------------------------------------------------------------
// 1) QKV projections: grid (E/BN=32, S/BM=16, 3)
// ---------------------------------------------------------------------------
__global__ void __launch_bounds__(NTHREADS)
qkv_kernel(const float* __restrict__ X,
           const float* __restrict__ wq,
           const float* __restrict__ wk,
           const float* __restrict__ wv)
{
    const float* W;
    float* O;
    if (blockIdx.z == 0)      { W = wq; O = g_q; }
    else if (blockIdx.z == 1) { W = wk; O = g_k; }
    else                      { W = wv; O = g_v; }
    gemm_tile<false>(X, E_, W, E_, O, E_,
                     blockIdx.y * BM, blockIdx.x * BN, 0, E_);
}

// ---------------------------------------------------------------------------
// 2) RoPE on first RD dims of each head of Q and K (in place)
// ---------------------------------------------------------------------------
__global__ void rope_kernel(const int* __restrict__ pos_ids)
{
    int idx = blockIdx.x * blockDim.x + threadIdx.x;  // over S*H*(RD/2)
    if (idx >= S_ * H_ * (RD_ / 2)) return;
    int i = idx & 31;            // pair index 0..31
    int h = (idx >> 5) & (H_ - 1);
    int s = idx >> 9;

    double pos = (double)pos_ids[s];
    double inv = pow(10000.0, -(double)(2 * i) / (double)RD_);
    double ang = pos * inv;
    double sd, cd;
    sincos(ang, &sd, &cd);
    float sn = (float)sd, cs = (float)cd;

    size_t base = (size_t)s * E_ + h * D_ + 2 * i;
    float q0 = g_q[base], q1 = g_q[base + 1];
    g_q[base]     = q0 * cs - q1 * sn;
    g_q[base + 1] = q1 * cs + q0 * sn;
    float k0 = g_k[base], k1 = g_k[base + 1];
    g_k[base]     = k0 * cs - k1 * sn;
    g_k[base + 1] = k1 * cs + k0 * sn;
}

// ---------------------------------------------------------------------------
// 3) scores[h] = Q_h @ K_h^T  -- skip tiles fully above the causal diagonal
//    grid (S/BN=16, S/BM=16, H=16)
// ---------------------------------------------------------------------------
__global__ void __launch_bounds__(NTHREADS)
scores_kernel()
{
    if (blockIdx.x > blockIdx.y) return;  // key-tile entirely in masked region
    int h = blockIdx.z;
    gemm_tile<true>(g_q + h * D_, E_,
                    g_k + h * D_, E_,
                    g_scores + (size_t)h * S_ * S_, S_,
                    blockIdx.y * BM, blockIdx.x * BN, 0, D_);
}

// ---------------------------------------------------------------------------
// 4) causal softmax in-place. One block per (q,h) row.
//    Zero-fills k in (q, kLimit) where kLimit = diagonal-tile end, so the PV
//    GEMM can read full tiles up to the diagonal tile.
// ---------------------------------------------------------------------------
__global__ void __launch_bounds__(NTHREADS)
softmax_kernel()
{
    const int q = blockIdx.x;
    const int h = blockIdx.y;
    float* row = g_scores + ((size_t)h * S_ + q) * S_;
    const int L = q + 1;
    const float scale = 0.0625f;  // 1/sqrt(256)
    const int tid = threadIdx.x;
    __shared__ float red[NTHREADS];

    // max
    float m = -INFINITY;
    for (int k = tid; k < L; k += NTHREADS) m = fmaxf(m, row[k] * scale);
    red[tid] = m; __syncthreads();
#pragma unroll
    for (int s = NTHREADS / 2; s > 0; s >>= 1) {
        if (tid < s) red[tid] = fmaxf(red[tid], red[tid + s]);
        __syncthreads();
    }
    m = red[0];
    __syncthreads();

    // sum
    float sum = 0.0f;
    for (int k = tid; k < L; k += NTHREADS) sum += expf(row[k] * scale - m);
    red[tid] = sum; __syncthreads();
#pragma unroll
    for (int s = NTHREADS / 2; s > 0; s >>= 1) {
        if (tid < s) red[tid] += red[tid + s];
        __syncthreads();
    }
    sum = red[0];
    const float inv = 1.0f / sum;

    // normalize; zero-fill up to end of diagonal tile
    const int kLimit = ((q >> 7) + 1) << 7;
    for (int k = tid; k < kLimit; k += NTHREADS)
        row[k] = (k < L) ? expf(row[k] * scale - m) * inv : 0.0f;
}

// ---------------------------------------------------------------------------
// 5) attn[h] = P_h @ V_h -- k-loop clipped at diagonal tile (probs beyond = 0)
//    grid (D/BN=2, S/BM=16, H=16)
// ---------------------------------------------------------------------------
__global__ void __launch_bounds__(NTHREADS)
pv_kernel()
{
    int h = blockIdx.z;
    int kEnd = (blockIdx.y + 1) * BM;  // causal clip
    gemm_tile<false>(g_scores + (size_t)h * S_ * S_, S_,
                     g_v + h * D_, E_,
                     g_attn + h * D_, E_,
                     blockIdx.y * BM, blockIdx.x * BN, 0, kEnd);
}

// ---------------------------------------------------------------------------
// 6) out = attn @ Wo : grid (E/BN=32, S/BM=16)
// ---------------------------------------------------------------------------
__global__ void __launch_bounds__(NTHREADS)
out_kernel(const float* __restrict__ wo, float* __restrict__ out)
{
    gemm_tile<false>(g_attn, E_, wo, E_, out, E_,
                     blockIdx.y * BM, blockIdx.x * BN, 0, E_);
}

// ---------------------------------------------------------------------------
extern "C" void kernel_launch(void* const* d_in, const int* in_sizes, int n_in,
                              void* d_out, int out_size)
{
    const float* X  = (const float*)d_in[0];
    const float* wq = (const float*)d_in[1];
    const float* wk = (const float*)d_in[2];
    const float* wv = (const float*)d_in[3];
    const float* wo = (const float*)d_in[4];
    const int*  pos = (const int*)d_in[5];
    float* out = (float*)d_out;

    qkv_kernel<<<dim3(E_ / BN, S_ / BM, 3), NTHREADS>>>(X, wq, wk, wv);

    int ropeN = S_ * H_ * (RD_ / 2);
    rope_kernel<<<(ropeN + 255) / 256, 256>>>(pos);

    scores_kernel<<<dim3(S_ / BN, S_ / BM, H_), NTHREADS>>>();

    softmax_kernel<<<dim3(S_, H_), NTHREADS>>>();

    pv_kernel<<<dim3(D_ / BN, S_ / BM, H_), NTHREADS>>>();

    out_kernel<<<dim3(E_ / BN, S_ / BM), NTHREADS>>>(wo, out);
}

// round 9
// speedup vs baseline: 1.5461x; 1.5461x over previous
#include <cuda_runtime.h>
#include <cuda_bf16.h>
#include <cuda_pipeline.h>
#include <mma.h>
#include <math.h>

using namespace nvcuda;

// Problem constants
#define S_   2048
#define E_   4096
#define H_   16
#define D_   256
#define RD_  64

// GEMM tiling (bf16 mma)
#define BM   128
#define BN   128
#define BKC  32              // k-elements per smem chunk
#define LDA_S 40             // 32 + 8 pad (bf16 elems), 80B rows (16B-aligned)
#define LDB_S 136            // 128 + 8 pad, 272B rows (16B-aligned)
#define AS_ELEMS (128 * LDA_S)       // 5120
#define BS_ELEMS 5120                // max(32*136=4352, 128*40=5120)
#define NTH  256

// ---------------------------------------------------------------------------
// Device-global scratch (allocation-guard-safe)
// ---------------------------------------------------------------------------
__device__ float g_q[(size_t)S_ * E_];
__device__ float g_k[(size_t)S_ * E_];
__device__ float g_v[(size_t)S_ * E_];
__device__ float g_attn[(size_t)S_ * E_];
__device__ float g_scores[(size_t)H_ * S_ * S_];     // 256 MB

// bf16 hi/lo splits
__device__ __nv_bfloat16 g_xhi[(size_t)S_ * E_],  g_xlo[(size_t)S_ * E_];
__device__ __nv_bfloat16 g_wqhi[(size_t)E_ * E_], g_wqlo[(size_t)E_ * E_];
__device__ __nv_bfloat16 g_wkhi[(size_t)E_ * E_], g_wklo[(size_t)E_ * E_];
__device__ __nv_bfloat16 g_wvhi[(size_t)E_ * E_], g_wvlo[(size_t)E_ * E_];
__device__ __nv_bfloat16 g_wohi[(size_t)E_ * E_], g_wolo[(size_t)E_ * E_];
__device__ __nv_bfloat16 g_qhi[(size_t)S_ * E_],  g_qlo[(size_t)S_ * E_];
__device__ __nv_bfloat16 g_khi[(size_t)S_ * E_],  g_klo[(size_t)S_ * E_];
__device__ __nv_bfloat16 g_vhi[(size_t)S_ * E_],  g_vlo[(size_t)S_ * E_];
__device__ __nv_bfloat16 g_ahi[(size_t)S_ * E_],  g_alo[(size_t)S_ * E_];
__device__ __nv_bfloat16 g_phi[(size_t)H_ * S_ * S_], g_plo[(size_t)H_ * S_ * S_];

// ---------------------------------------------------------------------------
// fp32 -> (hi, lo) bf16 split
// ---------------------------------------------------------------------------
__global__ void split_kernel(const float* __restrict__ src,
                             __nv_bfloat16* __restrict__ hi,
                             __nv_bfloat16* __restrict__ lo, int n4)
{
    int i = blockIdx.x * blockDim.x + threadIdx.x;
    int stride = gridDim.x * blockDim.x;
    for (; i < n4; i += stride) {
        float4 v = ((const float4*)src)[i];
        __nv_bfloat16 h0 = __float2bfloat16_rn(v.x);
        __nv_bfloat16 h1 = __float2bfloat16_rn(v.y);
        __nv_bfloat16 h2 = __float2bfloat16_rn(v.z);
        __nv_bfloat16 h3 = __float2bfloat16_rn(v.w);
        __nv_bfloat16 l0 = __float2bfloat16_rn(v.x - __bfloat162float(h0));
        __nv_bfloat16 l1 = __float2bfloat16_rn(v.y - __bfloat162float(h1));
        __nv_bfloat16 l2 = __float2bfloat16_rn(v.z - __bfloat162float(h2));
        __nv_bfloat16 l3 = __float2bfloat16_rn(v.w - __bfloat162float(h3));
        __nv_bfloat162* hp = (__nv_bfloat162*)hi;
        __nv_bfloat162* lp = (__nv_bfloat162*)lo;
        hp[2 * i]     = __nv_bfloat162(h0, h1);
        hp[2 * i + 1] = __nv_bfloat162(h2, h3);
        lp[2 * i]     = __nv_bfloat162(l0, l1);
        lp[2 * i + 1] = __nv_bfloat162(l2, l3);
    }
}

// ---------------------------------------------------------------------------
// Chunk loader: A tile 128x32 (row-major k-contig), B tile:
//   !TRANSB : 32(k) x 128(n) row-major n-contig  -> Bs[k][n] stride LDB_S
//    TRANSB : B rows are n, k-contig             -> Bs[n][k] stride LDA_S
// ---------------------------------------------------------------------------
template <bool TRANSB>
__device__ __forceinline__ void load_chunk(
    __nv_bfloat16* as, __nv_bfloat16* bs,
    const __nv_bfloat16* __restrict__ A, int lda,
    const __nv_bfloat16* __restrict__ B, int ldb,
    int m0, int n0, int kt, int tid)
{
    {
        int r = tid >> 1, c = (tid & 1) * 16;
        const __nv_bfloat16* src = A + (size_t)(m0 + r) * lda + kt + c;
        __nv_bfloat16* dst = as + r * LDA_S + c;
        __pipeline_memcpy_async(dst,     src,     16);
        __pipeline_memcpy_async(dst + 8, src + 8, 16);
    }
    if (TRANSB) {
        int r = tid >> 1, c = (tid & 1) * 16;
        const __nv_bfloat16* src = B + (size_t)(n0 + r) * ldb + kt + c;
        __nv_bfloat16* dst = bs + r * LDA_S + c;
        __pipeline_memcpy_async(dst,     src,     16);
        __pipeline_memcpy_async(dst + 8, src + 8, 16);
    } else {
        int r = tid >> 3, c = (tid & 7) * 16;
        const __nv_bfloat16* src = B + (size_t)(kt + r) * ldb + n0 + c;
        __nv_bfloat16* dst = bs + r * LDB_S + c;
        __pipeline_memcpy_async(dst,     src,     16);
        __pipeline_memcpy_async(dst + 8, src + 8, 16);
    }
}

// ---------------------------------------------------------------------------
// 3xBF16 GEMM core: C = Ahi*Bhi + Ahi*Blo + Alo*Bhi over k in [k0,k1).
// 128x128 CTA tile, 8 warps as 4(m) x 2(n), warp tile 32x64.
// Double-buffered cp.async pipeline.
// ---------------------------------------------------------------------------
template <bool TRANSB>
__device__ void gemm3_tile(
    const __nv_bfloat16* __restrict__ Ahi, const __nv_bfloat16* __restrict__ Alo, int lda,
    const __nv_bfloat16* __restrict__ Bhi, const __nv_bfloat16* __restrict__ Blo, int ldb,
    float* __restrict__ C, int ldc,
    int m0, int n0, int k0, int k1)
{
    __shared__ __nv_bfloat16 As[2][AS_ELEMS];
    __shared__ __nv_bfloat16 Bs[2][BS_ELEMS];

    const int tid = threadIdx.x;
    const int wid = tid >> 5;
    const int wm = wid & 3;      // 32-row band
    const int wn = wid >> 2;     // 64-col band

    wmma::fragment<wmma::accumulator, 16, 16, 16, float> acc[2][4];
#pragma unroll
    for (int i = 0; i < 2; ++i)
#pragma unroll
        for (int j = 0; j < 4; ++j) wmma::fill_fragment(acc[i][j], 0.0f);

    const int nch = (k1 - k0) / BKC;
    const int total = nch * 3;
    const __nv_bfloat16* Ap[3] = {Ahi, Ahi, Alo};
    const __nv_bfloat16* Bp[3] = {Bhi, Blo, Bhi};

    load_chunk<TRANSB>(As[0], Bs[0], Ap[0], lda, Bp[0], ldb, m0, n0, k0, tid);
    __pipeline_commit();

    for (int c = 0; c < total; ++c) {
        int nxt = c + 1;
        if (nxt < total) {
            int p  = nxt / nch;
            int kk = k0 + (nxt % nch) * BKC;
            load_chunk<TRANSB>(As[nxt & 1], Bs[nxt & 1], Ap[p], lda, Bp[p], ldb,
                               m0, n0, kk, tid);
        }
        __pipeline_commit();
        __pipeline_wait_prior(1);
        __syncthreads();

        const __nv_bfloat16* as = As[c & 1];
        const __nv_bfloat16* bs = Bs[c & 1];
#pragma unroll
        for (int ks = 0; ks < 2; ++ks) {
            wmma::fragment<wmma::matrix_a, 16, 16, 16, __nv_bfloat16, wmma::row_major> af[2];
#pragma unroll
            for (int i = 0; i < 2; ++i)
                wmma::load_matrix_sync(af[i], as + (wm * 32 + i * 16) * LDA_S + ks * 16, LDA_S);
            if (TRANSB) {
                wmma::fragment<wmma::matrix_b, 16, 16, 16, __nv_bfloat16, wmma::col_major> bf[4];
#pragma unroll
                for (int j = 0; j < 4; ++j)
                    wmma::load_matrix_sync(bf[j], bs + (wn * 64 + j * 16) * LDA_S + ks * 16, LDA_S);
#pragma unroll
                for (int i = 0; i < 2; ++i)
#pragma unroll
                    for (int j = 0; j < 4; ++j)
                        wmma::mma_sync(acc[i][j], af[i], bf[j], acc[i][j]);
            } else {
                wmma::fragment<wmma::matrix_b, 16, 16, 16, __nv_bfloat16, wmma::row_major> bf[4];
#pragma unroll
                for (int j = 0; j < 4; ++j)
                    wmma::load_matrix_sync(bf[j], bs + ks * 16 * LDB_S + wn * 64 + j * 16, LDB_S);
#pragma unroll
                for (int i = 0; i < 2; ++i)
#pragma unroll
                    for (int j = 0; j < 4; ++j)
                        wmma::mma_sync(acc[i][j], af[i], bf[j], acc[i][j]);
            }
        }
        __syncthreads();
    }

#pragma unroll
    for (int i = 0; i < 2; ++i)
#pragma unroll
        for (int j = 0; j < 4; ++j)
            wmma::store_matrix_sync(
                C + (size_t)(m0 + wm * 32 + i * 16) * ldc + n0 + wn * 64 + j * 16,
                acc[i][j], ldc, wmma::mem_row_major);
}

// ---------------------------------------------------------------------------
// 1) QKV projections: grid (E/BN=32, S/BM=16, 3)
// ---------------------------------------------------------------------------
__global__ void __launch_bounds__(NTH)
qkv_kernel()
{
    const __nv_bfloat16 *Wh, *Wl;
    float* O;
    if (blockIdx.z == 0)      { Wh = g_wqhi; Wl = g_wqlo; O = g_q; }
    else if (blockIdx.z == 1) { Wh = g_wkhi; Wl = g_wklo; O = g_k; }
    else                      { Wh = g_wvhi; Wl = g_wvlo; O = g_v; }
    gemm3_tile<false>(g_xhi, g_xlo, E_, Wh, Wl, E_, O, E_,
                      blockIdx.y * BM, blockIdx.x * BN, 0, E_);
}

// ---------------------------------------------------------------------------
// 2) RoPE on first RD dims of each head of Q and K (fp32 in-place)
// ---------------------------------------------------------------------------
__global__ void rope_kernel(const int* __restrict__ pos_ids)
{
    int idx = blockIdx.x * blockDim.x + threadIdx.x;   // S*H*(RD/2)
    if (idx >= S_ * H_ * (RD_ / 2)) return;
    int i = idx & 31;
    int h = (idx >> 5) & (H_ - 1);
    int s = idx >> 9;

    double pos = (double)pos_ids[s];
    double inv = pow(10000.0, -(double)(2 * i) / (double)RD_);
    double sd, cd;
    sincos(pos * inv, &sd, &cd);
    float sn = (float)sd, cs = (float)cd;

    size_t base = (size_t)s * E_ + h * D_ + 2 * i;
    float q0 = g_q[base], q1 = g_q[base + 1];
    g_q[base]     = q0 * cs - q1 * sn;
    g_q[base + 1] = q1 * cs + q0 * sn;
    float k0 = g_k[base], k1 = g_k[base + 1];
    g_k[base]     = k0 * cs - k1 * sn;
    g_k[base + 1] = k1 * cs + k0 * sn;
}

// ---------------------------------------------------------------------------
// 3) scores[h] = Q_h @ K_h^T (causal tile skip): grid (16,16,16)
// ---------------------------------------------------------------------------
__global__ void __launch_bounds__(NTH)
scores_kernel()
{
    if (blockIdx.x > blockIdx.y) return;
    int h = blockIdx.z;
    gemm3_tile<true>(g_qhi + h * D_, g_qlo + h * D_, E_,
                     g_khi + h * D_, g_klo + h * D_, E_,
                     g_scores + (size_t)h * S_ * S_, S_,
                     blockIdx.y * BM, blockIdx.x * BN, 0, D_);
}

// ---------------------------------------------------------------------------
// 4) causal softmax: read fp32 scores, write probs as hi/lo bf16,
//    zero-filled to the end of the diagonal tile.
// ---------------------------------------------------------------------------
__global__ void __launch_bounds__(NTH)
softmax_kernel()
{
    const int q = blockIdx.x;
    const int h = blockIdx.y;
    const float* row = g_scores + ((size_t)h * S_ + q) * S_;
    __nv_bfloat16* phi = g_phi + ((size_t)h * S_ + q) * S_;
    __nv_bfloat16* plo = g_plo + ((size_t)h * S_ + q) * S_;
    const int L = q + 1;
    const float scale = 0.0625f;   // 1/sqrt(256)
    const int tid = threadIdx.x;
    __shared__ float red[NTH];

    float m = -INFINITY;
    for (int k = tid; k < L; k += NTH) m = fmaxf(m, row[k] * scale);
    red[tid] = m; __syncthreads();
#pragma unroll
    for (int s = NTH / 2; s > 0; s >>= 1) {
        if (tid < s) red[tid] = fmaxf(red[tid], red[tid + s]);
        __syncthreads();
    }
    m = red[0];
    __syncthreads();

    float sum = 0.0f;
    for (int k = tid; k < L; k += NTH) sum += expf(row[k] * scale - m);
    red[tid] = sum; __syncthreads();
#pragma unroll
    for (int s = NTH / 2; s > 0; s >>= 1) {
        if (tid < s) red[tid] += red[tid + s];
        __syncthreads();
    }
    const float inv = 1.0f / red[0];

    const int kLimit = ((q >> 7) + 1) << 7;
    for (int k = tid; k < kLimit; k += NTH) {
        float p = (k < L) ? expf(row[k] * scale - m) * inv : 0.0f;
        __nv_bfloat16 hi = __float2bfloat16_rn(p);
        __nv_bfloat16 lo = __float2bfloat16_rn(p - __bfloat162float(hi));
        phi[k] = hi;
        plo[k] = lo;
    }
}

// ---------------------------------------------------------------------------
// 5) attn[h] = P_h @ V_h, k clipped at diagonal tile: grid (2,16,16)
// ---------------------------------------------------------------------------
__global__ void __launch_bounds__(NTH)
pv_kernel()
{
    int h = blockIdx.z;
    int kEnd = (blockIdx.y + 1) * BM;
    gemm3_tile<false>(g_phi + (size_t)h * S_ * S_, g_plo + (size_t)h * S_ * S_, S_,
                      g_vhi + h * D_, g_vlo + h * D_, E_,
                      g_attn + h * D_, E_,
                      blockIdx.y * BM, blockIdx.x * BN, 0, kEnd);
}

// ---------------------------------------------------------------------------
// 6) out = attn @ Wo : grid (32,16)
// ---------------------------------------------------------------------------
__global__ void __launch_bounds__(NTH)
out_kernel(float* __restrict__ out)
{
    gemm3_tile<false>(g_ahi, g_alo, E_, g_wohi, g_wolo, E_, out, E_,
                      blockIdx.y * BM, blockIdx.x * BN, 0, E_);
}

// ---------------------------------------------------------------------------
extern "C" void kernel_launch(void* const* d_in, const int* in_sizes, int n_in,
                              void* d_out, int out_size)
{
    const float* X  = (const float*)d_in[0];
    const float* wq = (const float*)d_in[1];
    const float* wk = (const float*)d_in[2];
    const float* wv = (const float*)d_in[3];
    const float* wo = (const float*)d_in[4];
    const int*  pos = (const int*)d_in[5];
    float* out = (float*)d_out;

    __nv_bfloat16 *xhi, *xlo, *wqhi, *wqlo, *wkhi, *wklo, *wvhi, *wvlo, *wohi, *wolo;
    __nv_bfloat16 *qhi, *qlo, *khi, *klo, *vhi, *vlo, *ahi, *alo;
    float *qf, *kf, *vf, *af;
    cudaGetSymbolAddress((void**)&xhi,  g_xhi);  cudaGetSymbolAddress((void**)&xlo,  g_xlo);
    cudaGetSymbolAddress((void**)&wqhi, g_wqhi); cudaGetSymbolAddress((void**)&wqlo, g_wqlo);
    cudaGetSymbolAddress((void**)&wkhi, g_wkhi); cudaGetSymbolAddress((void**)&wklo, g_wklo);
    cudaGetSymbolAddress((void**)&wvhi, g_wvhi); cudaGetSymbolAddress((void**)&wvlo, g_wvlo);
    cudaGetSymbolAddress((void**)&wohi, g_wohi); cudaGetSymbolAddress((void**)&wolo, g_wolo);
    cudaGetSymbolAddress((void**)&qhi,  g_qhi);  cudaGetSymbolAddress((void**)&qlo,  g_qlo);
    cudaGetSymbolAddress((void**)&khi,  g_khi);  cudaGetSymbolAddress((void**)&klo,  g_klo);
    cudaGetSymbolAddress((void**)&vhi,  g_vhi);  cudaGetSymbolAddress((void**)&vlo,  g_vlo);
    cudaGetSymbolAddress((void**)&ahi,  g_ahi);  cudaGetSymbolAddress((void**)&alo,  g_alo);
    cudaGetSymbolAddress((void**)&qf, g_q); cudaGetSymbolAddress((void**)&kf, g_k);
    cudaGetSymbolAddress((void**)&vf, g_v); cudaGetSymbolAddress((void**)&af, g_attn);

    const int SB = 256;
    const int nX4 = S_ * E_ / 4;   // 2.1M float4
    const int nW4 = E_ * E_ / 4;   // 4.2M float4

    // input splits
    split_kernel<<<4096, SB>>>(X,  xhi,  xlo,  nX4);
    split_kernel<<<8192, SB>>>(wq, wqhi, wqlo, nW4);
    split_kernel<<<8192, SB>>>(wk, wkhi, wklo, nW4);
    split_kernel<<<8192, SB>>>(wv, wvhi, wvlo, nW4);
    split_kernel<<<8192, SB>>>(wo, wohi, wolo, nW4);

    // projections
    qkv_kernel<<<dim3(E_ / BN, S_ / BM, 3), NTH>>>();

    // RoPE (fp32 q,k in place)
    int ropeN = S_ * H_ * (RD_ / 2);
    rope_kernel<<<(ropeN + 255) / 256, 256>>>(pos);

    // splits of q, k (post-rope) and v
    split_kernel<<<4096, SB>>>(qf, qhi, qlo, nX4);
    split_kernel<<<4096, SB>>>(kf, khi, klo, nX4);
    split_kernel<<<4096, SB>>>(vf, vhi, vlo, nX4);

    // attention
    scores_kernel<<<dim3(S_ / BN, S_ / BM, H_), NTH>>>();
    softmax_kernel<<<dim3(S_, H_), NTH>>>();
    pv_kernel<<<dim3(D_ / BN, S_ / BM, H_), NTH>>>();

    // output projection
    split_kernel<<<4096, SB>>>(af, ahi, alo, nX4);
    out_kernel<<<dim3(E_ / BN, S_ / BM), NTH>>>(out);
}